// round 4
// baseline (speedup 1.0000x reference)
#include <cuda_runtime.h>
#include <cstdint>

#define BB 32
#define SS 8192
#define DD 64
#define FF 128
#define CS 128
#define NCHUNK (SS / CS)

// Scratch (device globals — no allocation allowed in kernel_launch)
__device__ float g_a [BB * SS * FF];   // k_s
__device__ float g_c [BB * SS * FF];   // k_s * v_f
__device__ float g_qs[BB * SS * FF];   // q_s
__device__ float g_pA[NCHUNK * BB * FF];
__device__ float g_pC[NCHUNK * BB * FF];
__device__ float g_wfrag[16384];       // W fragments: [plane][kstep][nt][lane][2]

// tf32 round-to-nearest
__device__ __forceinline__ uint32_t f2tf32(float x) {
    uint32_t r;
    asm("cvt.rna.tf32.f32 %0, %1;" : "=r"(r) : "f"(x));
    return r;
}

// m16n8k8 tf32 mma (legacy sm_80 path -> HMMA on Blackwell)
#define MMA_TF32(c, av, bv)                                                     \
    asm volatile("mma.sync.aligned.m16n8k8.row.col.f32.tf32.tf32.f32 "          \
        "{%0,%1,%2,%3}, {%4,%5,%6,%7}, {%8,%9}, {%0,%1,%2,%3};"                 \
        : "+f"((c)[0]), "+f"((c)[1]), "+f"((c)[2]), "+f"((c)[3])                \
        : "r"(__float_as_uint((av).x)), "r"(__float_as_uint((av).y)),           \
          "r"(__float_as_uint((av).z)), "r"(__float_as_uint((av).w)),           \
          "r"(__float_as_uint((bv).x)), "r"(__float_as_uint((bv).y)))

// ---------------------------------------------------------------------------
// SMEM float-index layout (total 52224 floats = 204 KB):
//   [0, 16384)      Wfrag: plane*8192 + kstep*1024 + nt4*64 + lane*2 + reg
//   [16384, 32768)  Astage: plane*8192 + (rb*8+kstep)*128 + slot*4 + reg
//                   (slot = L ^ kstep, L = (rp%8)*4 + (kp%4))
//   [32768, 49152)  vbuf: w*2048 + (rr*4+nt)*128 + lane*4 + reg
//   [49152, 53248)  psum: (col*2 + stream)*16 + wm*8 + group
// ---------------------------------------------------------------------------
#define SM_WF 0
#define SM_AS 16384
#define SM_VB 32768
#define SM_PS 49152
#define SM_FLOATS 53248

// ---------------------------------------------------------------------------
// Setup: W -> (big, small) tf32 fragments in gmem, fragment order (once).
// ---------------------------------------------------------------------------
__global__ void wfrag_setup(const float* __restrict__ w)
{
    for (int o = threadIdx.x; o < 16384; o += 128) {
        const int plane = o >> 13;
        const int rem   = o & 8191;
        const int kstep = rem >> 10;
        const int rem2  = rem & 1023;
        const int nt    = rem2 >> 6;
        const int rem3  = rem2 & 63;
        const int lane  = rem3 >> 1;
        const int r     = rem3 & 1;
        const int d = kstep * 8 + (lane & 3) + r * 4;
        const int f = nt * 8 + (lane >> 2);
        const float val = w[d * FF + f];
        const uint32_t big = f2tf32(val);
        const uint32_t out = plane ? f2tf32(val - __uint_as_float(big)) : big;
        g_wfrag[o] = __uint_as_float(out);
    }
}

// Convert one 128x64 input tile -> exp -> split tf32 -> Astage. 256 threads.
#define CONV_INPUT(xptr)                                                        \
    do {                                                                        \
        _Pragma("unroll")                                                       \
        for (int j = 0; j < 8; j++) {                                           \
            const int f4  = tid + j * 256;                                      \
            const int row = f4 >> 4;                                            \
            const int c4  = f4 & 15;                                            \
            float4 e = *(const float4*)&(xptr)[row * DD + c4 * 4];              \
            float ev[4];                                                        \
            ev[0] = __expf(e.x); ev[1] = __expf(e.y);                           \
            ev[2] = __expf(e.z); ev[3] = __expf(e.w);                           \
            const int rb = row >> 4;                                            \
            const int rp = row & 15;                                            \
            _Pragma("unroll")                                                   \
            for (int ee = 0; ee < 4; ee++) {                                    \
                const int kk = c4 * 4 + ee;                                     \
                const int kstep = kk >> 3;                                      \
                const int kp = kk & 7;                                          \
                const int L = (rp & 7) * 4 + (kp & 3);                          \
                const int slot = L ^ kstep;                                     \
                const int reg = (rp >> 3) + 2 * (kp >> 2);                      \
                const int fi = (rb * 8 + kstep) * 128 + slot * 4 + reg;         \
                const uint32_t big = f2tf32(ev[ee]);                            \
                sm[SM_AS + fi] = __uint_as_float(big);                          \
                sm[SM_AS + 8192 + fi] =                                         \
                    __uint_as_float(f2tf32(ev[ee] - __uint_as_float(big)));     \
            }                                                                   \
        }                                                                       \
    } while (0)

// 3-pass split-tf32 mma into acc[4][4][4] (zeroed first).
// Warp covers rows [wm*64, wm*64+64) (rb = wm*4+rr), cols [wn*32, wn*32+32).
#define MMA_ALL()                                                               \
    do {                                                                        \
        _Pragma("unroll") for (int _r = 0; _r < 4; _r++)                        \
        _Pragma("unroll") for (int _n = 0; _n < 4; _n++)                        \
        _Pragma("unroll") for (int _e = 0; _e < 4; _e++) acc[_r][_n][_e] = 0.f; \
        _Pragma("unroll")                                                       \
        for (int p = 0; p < 3; p++) {                                           \
            const float* Abase = sm + SM_AS + ((p == 2) ? 8192 : 0);            \
            const float* Bbase = sm + SM_WF + ((p == 1) ? 8192 : 0);            \
            _Pragma("unroll")                                                   \
            for (int kstep = 0; kstep < 8; kstep++) {                           \
                float2 Bv[4];                                                   \
                _Pragma("unroll")                                               \
                for (int nt = 0; nt < 4; nt++)                                  \
                    Bv[nt] = *(const float2*)&Bbase[kstep * 1024 +              \
                        (wn * 4 + nt) * 64 + lane * 2];                         \
                _Pragma("unroll")                                               \
                for (int rr = 0; rr < 4; rr++) {                                \
                    const int rb = wm * 4 + rr;                                 \
                    const float4 Av = *(const float4*)&Abase[                   \
                        (rb * 8 + kstep) * 128 + (lane ^ kstep) * 4];           \
                    _Pragma("unroll")                                           \
                    for (int nt = 0; nt < 4; nt++)                              \
                        MMA_TF32(acc[rr][nt], Av, Bv[nt]);                      \
                }                                                               \
            }                                                                   \
        }                                                                       \
    } while (0)

// ---------------------------------------------------------------------------
// Kernel 1: features via split-tf32 mma.sync + spike gates + fused chunk sums.
// CTA = 128 s-rows (one chunk) x 128 F, 256 threads / 8 warps.
// ---------------------------------------------------------------------------
__global__ __launch_bounds__(256)
void featgate_mma(const float* __restrict__ q, const float* __restrict__ k,
                  const float* __restrict__ v)
{
    extern __shared__ float sm[];
    const int tid   = threadIdx.x;
    const int w     = tid >> 5;
    const int lane  = tid & 31;
    const int group = lane >> 2;
    const int tig   = lane & 3;
    const int wn    = w & 3;    // N-split
    const int wm    = w >> 2;   // M-split
    const int b  = blockIdx.y;
    const int ch = blockIdx.x;
    const size_t ibase = ((size_t)b * SS + ch * CS) * DD;
    const size_t obase = ((size_t)b * SS + ch * CS) * FF;

    // Load W fragments (coalesced identity copy)
#pragma unroll
    for (int i = tid * 4; i < 16384; i += 1024)
        *(float4*)&sm[SM_WF + i] = *(const float4*)&g_wfrag[i];

    float acc[4][4][4];

    // ===== V =====
    CONV_INPUT(v + ibase);
    __syncthreads();
    MMA_ALL();
#pragma unroll
    for (int rr = 0; rr < 4; rr++)
#pragma unroll
        for (int nt = 0; nt < 4; nt++)
            *(float4*)&sm[SM_VB + w * 2048 + (rr * 4 + nt) * 128 + lane * 4] =
                *(float4*)acc[rr][nt];
    __syncthreads();

    // ===== K =====
    CONV_INPUT(k + ibase);
    __syncthreads();
    MMA_ALL();
    {
        float psA[4][2], psC[4][2];
#pragma unroll
        for (int nt = 0; nt < 4; nt++) { psA[nt][0] = psA[nt][1] = psC[nt][0] = psC[nt][1] = 0.f; }
#pragma unroll
        for (int rr = 0; rr < 4; rr++) {
#pragma unroll
            for (int nt = 0; nt < 4; nt++) {
                const float4 vv = *(const float4*)&sm[SM_VB + w * 2048 + (rr * 4 + nt) * 128 + lane * 4];
                const int col = wn * 32 + nt * 8 + tig * 2;
                const int r0  = (wm * 4 + rr) * 16 + group;
                const float k0 = acc[rr][nt][0], k1 = acc[rr][nt][1];
                const float k2 = acc[rr][nt][2], k3 = acc[rr][nt][3];
                const float a0 = (k0 > 0.5f) ? k0 : 0.f;
                const float a1 = (k1 > 0.5f) ? k1 : 0.f;
                const float a2 = (k2 > 0.5f) ? k2 : 0.f;
                const float a3 = (k3 > 0.5f) ? k3 : 0.f;
                const float c0 = a0 * vv.x, c1 = a1 * vv.y;
                const float c2 = a2 * vv.z, c3 = a3 * vv.w;
                *(float2*)&g_a[obase + (size_t)r0 * FF + col]       = make_float2(a0, a1);
                *(float2*)&g_a[obase + (size_t)(r0 + 8) * FF + col] = make_float2(a2, a3);
                *(float2*)&g_c[obase + (size_t)r0 * FF + col]       = make_float2(c0, c1);
                *(float2*)&g_c[obase + (size_t)(r0 + 8) * FF + col] = make_float2(c2, c3);
                psA[nt][0] += a0 + a2;  psA[nt][1] += a1 + a3;
                psC[nt][0] += c0 + c2;  psC[nt][1] += c1 + c3;
            }
        }
#pragma unroll
        for (int nt = 0; nt < 4; nt++)
#pragma unroll
            for (int par = 0; par < 2; par++) {
                const int col = wn * 32 + nt * 8 + tig * 2 + par;
                sm[SM_PS + (col * 2 + 0) * 16 + wm * 8 + group] = psA[nt][par];
                sm[SM_PS + (col * 2 + 1) * 16 + wm * 8 + group] = psC[nt][par];
            }
    }
    __syncthreads();

    // ===== Q =====
    CONV_INPUT(q + ibase);
    __syncthreads();
    MMA_ALL();
#pragma unroll
    for (int rr = 0; rr < 4; rr++) {
#pragma unroll
        for (int nt = 0; nt < 4; nt++) {
            const int col = wn * 32 + nt * 8 + tig * 2;
            const int r0  = (wm * 4 + rr) * 16 + group;
            const float q0 = acc[rr][nt][0], q1 = acc[rr][nt][1];
            const float q2 = acc[rr][nt][2], q3 = acc[rr][nt][3];
            *(float2*)&g_qs[obase + (size_t)r0 * FF + col] =
                make_float2((q0 > 0.5f) ? q0 : 0.f, (q1 > 0.5f) ? q1 : 0.f);
            *(float2*)&g_qs[obase + (size_t)(r0 + 8) * FF + col] =
                make_float2((q2 > 0.5f) ? q2 : 0.f, (q3 > 0.5f) ? q3 : 0.f);
        }
    }
    __syncthreads();

    // ===== chunk-sum reduction (replaces partial_kernel) =====
    if (tid < FF) {
        float sA = 0.f, sC = 0.f;
#pragma unroll
        for (int i = 0; i < 16; i++) {
            sA += sm[SM_PS + (tid * 2 + 0) * 16 + i];
            sC += sm[SM_PS + (tid * 2 + 1) * 16 + i];
        }
        g_pA[((size_t)ch * BB + b) * FF + tid] = sA;
        g_pC[((size_t)ch * BB + b) * FF + tid] = sC;
    }
}

// ---------------------------------------------------------------------------
// Kernel 2: finalize — chunk prefix from partials, in-chunk scan, output.
// ---------------------------------------------------------------------------
__global__ __launch_bounds__(128) void finalize_kernel(float* __restrict__ out)
{
    const int f  = threadIdx.x;
    const int b  = blockIdx.y;
    const int ch = blockIdx.x;

    float cA = 0.f, cC = 0.f;
    for (int p = 0; p < ch; p++) {
        cA += g_pA[((size_t)p * BB + b) * FF + f];
        cC += g_pC[((size_t)p * BB + b) * FF + f];
    }

    const size_t base = ((size_t)b * SS + (size_t)ch * CS) * FF + f;
#pragma unroll 4
    for (int s = 0; s < CS; s++) {
        const size_t i = base + (size_t)s * FF;
        cA += g_a[i];
        cC += g_c[i];
        out[i] = g_qs[i] * __fdividef(cC + 1e-8f, cA + 1e-8f);
    }
}

extern "C" void kernel_launch(void* const* d_in, const int* in_sizes, int n_in,
                              void* d_out, int out_size)
{
    const float* q = (const float*)d_in[0];
    const float* k = (const float*)d_in[1];
    const float* v = (const float*)d_in[2];
    const float* w = (const float*)d_in[3];
    float* out = (float*)d_out;

    wfrag_setup<<<1, 128>>>(w);

    cudaFuncSetAttribute(featgate_mma, cudaFuncAttributeMaxDynamicSharedMemorySize,
                         SM_FLOATS * 4);
    dim3 g1(NCHUNK, BB);
    featgate_mma<<<g1, 256, SM_FLOATS * 4>>>(q, k, v);

    finalize_kernel<<<g1, 128>>>(out);
}